// round 1
// baseline (speedup 1.0000x reference)
#include <cuda_runtime.h>

// Shapes (fixed for this problem)
#define M_   4096
#define B_   8
#define N_   512
#define FD_  128
#define BD_  128
#define BVD_ 6
#define H_   64

// Scratch (allocation-free rule: __device__ globals)
__device__ float g_F[M_ * H_];        // (m, h)   f = Wf @ fin.T + bf, transposed
__device__ float g_BF[B_ * H_ * N_];  // (b, h, n) b_feat
__device__ float g_BV[B_ * N_ * H_];  // (b, n, h) bv_feat (transposed for coalesced h reads)

// ---------------- prep: F[m][h] = Wf[h] . fin[m] + bf[h] -------------------
__global__ void __launch_bounds__(256) prep_f_kernel(
    const float* __restrict__ fin, const float* __restrict__ Wf,
    const float* __restrict__ bf)
{
    __shared__ float WfT[128 * 65];   // [d][h], padded stride 65 (bank-conflict-free)
    __shared__ float fsh[16][128];
    const int tid = threadIdx.x;
    const int m0  = blockIdx.x * 16;

    for (int i = tid; i < H_ * FD_; i += 256) {
        int h = i >> 7, d = i & 127;
        WfT[d * 65 + h] = Wf[i];
    }
    for (int i = tid; i < 16 * 128; i += 256)
        fsh[i >> 7][i & 127] = fin[m0 * FD_ + i];
    __syncthreads();

    const int h  = tid & 63;
    const int r0 = tid >> 6;   // 0..3
    const float bfh = bf[h];
    for (int rr = 0; rr < 4; rr++) {
        int r = rr * 4 + r0;
        float acc = bfh;
        #pragma unroll 16
        for (int d = 0; d < 128; d++)
            acc += WfT[d * 65 + h] * fsh[r][d];
        g_F[(m0 + r) * H_ + h] = acc;
    }
}

// ---------- prep: BF[b][h][n] = Wb[h] . b_pre_in[b][:][n] + bb[h] ----------
__global__ void __launch_bounds__(256) prep_bf_kernel(
    const float* __restrict__ bpre, const float* __restrict__ Wb,
    const float* __restrict__ bb)
{
    __shared__ float Wbs[H_ * BD_];   // [h][d], 32KB
    const int tid = threadIdx.x;
    const int b   = blockIdx.x >> 3;
    const int n0  = (blockIdx.x & 7) * 64;

    for (int i = tid; i < H_ * BD_; i += 256) Wbs[i] = Wb[i];
    __syncthreads();

    const int n  = tid & 63;
    const int hb = (tid >> 6) * 16;
    const float* src = bpre + b * BD_ * N_ + n0 + n;

    float acc[16];
    #pragma unroll
    for (int hh = 0; hh < 16; hh++) acc[hh] = 0.f;

    for (int d = 0; d < BD_; d++) {
        float v = __ldg(src + d * N_);
        #pragma unroll
        for (int hh = 0; hh < 16; hh++)
            acc[hh] += Wbs[(hb + hh) * BD_ + d] * v;
    }
    #pragma unroll
    for (int hh = 0; hh < 16; hh++)
        g_BF[b * H_ * N_ + (hb + hh) * N_ + n0 + n] = acc[hh] + bb[hb + hh];
}

// ---------- prep: BV[b][n][h] = Wbv[h] . bv_in[b][:][n] + bbv[h] -----------
__global__ void __launch_bounds__(256) prep_bv_kernel(
    const float* __restrict__ bvin, const float* __restrict__ Wbv,
    const float* __restrict__ bbv)
{
    __shared__ float bvs[BVD_ * N_];  // 12KB, [c][n]
    const int tid = threadIdx.x;
    const int b   = blockIdx.x;

    for (int i = tid; i < BVD_ * N_; i += 256) bvs[i] = bvin[b * BVD_ * N_ + i];
    __syncthreads();

    const int h = tid & 63;
    const float w0 = Wbv[h * 6 + 0], w1 = Wbv[h * 6 + 1], w2 = Wbv[h * 6 + 2];
    const float w3 = Wbv[h * 6 + 3], w4 = Wbv[h * 6 + 4], w5 = Wbv[h * 6 + 5];
    const float bias = bbv[h];

    for (int i = tid; i < N_ * H_; i += 256) {
        int n = i >> 6;
        float acc = bias
                  + w0 * bvs[n]            + w1 * bvs[512 + n]
                  + w2 * bvs[1024 + n]     + w3 * bvs[1536 + n]
                  + w4 * bvs[2048 + n]     + w5 * bvs[2560 + n];
        g_BV[b * N_ * H_ + i] = acc;      // i = n*64 + h  (coalesced)
    }
}

// ------------------------------- main --------------------------------------
// One warp per row m. 8 rows per block, 512 blocks, 256 threads.
__global__ void __launch_bounds__(256) main_kernel(
    const int* __restrict__ batch, const float* __restrict__ Wo,
    const float* __restrict__ bo, float* __restrict__ out)
{
    __shared__ float Se[8][512];
    __shared__ float Sg[8][512];
    __shared__ float Fs[8][64];
    __shared__ float cat_sh[8][128];
    __shared__ int bsh[8];

    const int tid = threadIdx.x;
    const int w = tid >> 5, l = tid & 31;
    const int m0 = blockIdx.x * 8;

    if (tid < 8) bsh[tid] = batch[m0 + tid];
    for (int i = tid; i < 8 * 64; i += 256)
        Fs[i >> 6][i & 63] = g_F[m0 * H_ + i];
    __syncthreads();

    const int r = w;
    const int b = bsh[r];
    const float* BF = g_BF + b * H_ * N_;
    const float* BV = g_BV + b * N_ * H_;

    // ---- scores + per-lane running max ----
    float maxe = -1e30f, maxg = -1e30f;
    for (int ng = 0; ng < 16; ng++) {
        int n = ng * 32 + l;
        float ae = 0.f, ag = 0.f;
        #pragma unroll 16
        for (int h = 0; h < 32; h++)  ae += BF[h * N_ + n] * Fs[r][h];
        #pragma unroll 16
        for (int h = 32; h < 64; h++) ag += BF[h * N_ + n] * Fs[r][h];
        ae *= 0.125f; ag *= 0.125f;      // 1/sqrt(H)
        Se[r][n] = ae; Sg[r][n] = ag;
        maxe = fmaxf(maxe, ae); maxg = fmaxf(maxg, ag);
    }
    #pragma unroll
    for (int off = 16; off; off >>= 1) {
        maxe = fmaxf(maxe, __shfl_xor_sync(0xffffffffu, maxe, off));
        maxg = fmaxf(maxg, __shfl_xor_sync(0xffffffffu, maxg, off));
    }

    // ---- exp + sum (normalization deferred to the accumulator) ----
    float sume = 0.f, sumg = 0.f;
    for (int ng = 0; ng < 16; ng++) {
        int n = ng * 32 + l;
        float e = __expf(Se[r][n] - maxe); Se[r][n] = e; sume += e;
        float g = __expf(Sg[r][n] - maxg); Sg[r][n] = g; sumg += g;
    }
    #pragma unroll
    for (int off = 16; off; off >>= 1) {
        sume += __shfl_xor_sync(0xffffffffu, sume, off);
        sumg += __shfl_xor_sync(0xffffffffu, sumg, off);
    }
    const float rinve = 1.f / sume, rinvg = 1.f / sumg;
    __syncwarp();   // cross-lane smem reads of Se/Sg below

    // ---- out_euc/out_geo: lane owns h = l and h = l+32 ----
    float ae0 = 0.f, ae1 = 0.f, ag0 = 0.f, ag1 = 0.f;
    #pragma unroll 4
    for (int n = 0; n < N_; n++) {
        float we = Se[r][n], wg = Sg[r][n];
        float v0 = BV[n * H_ + l];
        float v1 = BV[n * H_ + 32 + l];
        ae0 += v0 * we; ae1 += v1 * we;
        ag0 += v0 * wg; ag1 += v1 * wg;
    }
    cat_sh[r][l]      = ae0 * rinve;
    cat_sh[r][32 + l] = ae1 * rinve;
    cat_sh[r][64 + l] = ag0 * rinvg;
    cat_sh[r][96 + l] = ag1 * rinvg;
    __syncwarp();

    // ---- final: out[m][j] = cat[m] . Wo[j] + bo[j], j = l and l+32 ----
    float acc0 = bo[l], acc1 = bo[32 + l];
    #pragma unroll 8
    for (int k = 0; k < 128; k++) {
        float c = cat_sh[r][k];
        acc0 += Wo[l * 128 + k] * c;
        acc1 += Wo[(32 + l) * 128 + k] * c;
    }
    out[(m0 + r) * H_ + l]      = acc0;
    out[(m0 + r) * H_ + 32 + l] = acc1;
}

// ------------------------------ launch -------------------------------------
extern "C" void kernel_launch(void* const* d_in, const int* in_sizes, int n_in,
                              void* d_out, int out_size)
{
    const float* fin  = (const float*)d_in[0];
    const int*   batch= (const int*)  d_in[1];
    const float* bpre = (const float*)d_in[2];
    const float* bvin = (const float*)d_in[3];
    const float* Wf   = (const float*)d_in[4];
    const float* bf   = (const float*)d_in[5];
    const float* Wb   = (const float*)d_in[6];
    const float* bb   = (const float*)d_in[7];
    const float* Wbv  = (const float*)d_in[8];
    const float* bbv  = (const float*)d_in[9];
    const float* Wo   = (const float*)d_in[10];
    const float* bo   = (const float*)d_in[11];
    float* out = (float*)d_out;

    prep_f_kernel<<<M_ / 16, 256>>>(fin, Wf, bf);
    prep_bf_kernel<<<B_ * (N_ / 64), 256>>>(bpre, Wb, bb);
    prep_bv_kernel<<<B_, 256>>>(bvin, Wbv, bbv);
    main_kernel<<<M_ / 8, 256>>>(batch, Wo, bo, out);
}

// round 3
// speedup vs baseline: 2.4544x; 2.4544x over previous
#include <cuda_runtime.h>

#define M_   4096
#define B_   8
#define N_   512
#define FD_  128
#define BD_  128
#define BVD_ 6
#define H_   64
#define TM   16       // rows per block
#define NT   128      // n-tile
#define TS   132      // padded tile row stride (floats)

__device__ float g_F[M_ * H_];        // (m, h)
__device__ float g_BF[B_ * H_ * N_];  // (b, h, n)
__device__ float g_BV[B_ * H_ * N_];  // (b, h, n)

// ---------------- prep: F[m][h] = Wf[h] . fin[m] + bf[h] -------------------
__global__ void __launch_bounds__(256) prep_f_kernel(
    const float* __restrict__ fin, const float* __restrict__ Wf,
    const float* __restrict__ bf)
{
    __shared__ float WfT[128 * 65];
    __shared__ float fsh[16][128];
    const int tid = threadIdx.x;
    const int m0  = blockIdx.x * 16;

    for (int i = tid; i < H_ * FD_; i += 256) {
        int h = i >> 7, d = i & 127;
        WfT[d * 65 + h] = Wf[i];
    }
    for (int i = tid; i < 16 * 128; i += 256)
        fsh[i >> 7][i & 127] = fin[m0 * FD_ + i];
    __syncthreads();

    const int h  = tid & 63;
    const int r0 = tid >> 6;
    const float bfh = bf[h];
    for (int rr = 0; rr < 4; rr++) {
        int r = rr * 4 + r0;
        float acc = bfh;
        #pragma unroll 16
        for (int d = 0; d < 128; d++)
            acc += WfT[d * 65 + h] * fsh[r][d];
        g_F[(m0 + r) * H_ + h] = acc;
    }
}

// ---------- prep: BF[b][h][n] = Wb[h] . b_pre_in[b][:][n] + bb[h] ----------
__global__ void __launch_bounds__(256) prep_bf_kernel(
    const float* __restrict__ bpre, const float* __restrict__ Wb,
    const float* __restrict__ bb)
{
    __shared__ float Wbs[H_ * BD_];
    const int tid = threadIdx.x;
    const int b   = blockIdx.x >> 3;
    const int n0  = (blockIdx.x & 7) * 64;

    for (int i = tid; i < H_ * BD_; i += 256) Wbs[i] = Wb[i];
    __syncthreads();

    const int n  = tid & 63;
    const int hb = (tid >> 6) * 16;
    const float* src = bpre + b * BD_ * N_ + n0 + n;

    float acc[16];
    #pragma unroll
    for (int hh = 0; hh < 16; hh++) acc[hh] = 0.f;

    for (int d = 0; d < BD_; d++) {
        float v = __ldg(src + d * N_);
        #pragma unroll
        for (int hh = 0; hh < 16; hh++)
            acc[hh] += Wbs[(hb + hh) * BD_ + d] * v;
    }
    #pragma unroll
    for (int hh = 0; hh < 16; hh++)
        g_BF[b * H_ * N_ + (hb + hh) * N_ + n0 + n] = acc[hh] + bb[hb + hh];
}

// ---------- prep: BV[b][h][n] = Wbv[h] . bv_in[b][:][n] + bbv[h] -----------
__global__ void __launch_bounds__(256) prep_bv_kernel(
    const float* __restrict__ bvin, const float* __restrict__ Wbv,
    const float* __restrict__ bbv)
{
    __shared__ float bvs[BVD_ * N_];
    const int tid = threadIdx.x;
    const int b   = blockIdx.x >> 3;
    const int h0  = (blockIdx.x & 7) * 8;

    for (int i = tid; i < BVD_ * N_; i += 256) bvs[i] = bvin[b * BVD_ * N_ + i];
    __syncthreads();

    #pragma unroll
    for (int hh = 0; hh < 8; hh++) {
        int h = h0 + hh;
        float w0 = __ldg(Wbv + h * 6 + 0), w1 = __ldg(Wbv + h * 6 + 1);
        float w2 = __ldg(Wbv + h * 6 + 2), w3 = __ldg(Wbv + h * 6 + 3);
        float w4 = __ldg(Wbv + h * 6 + 4), w5 = __ldg(Wbv + h * 6 + 5);
        float bias = __ldg(bbv + h);
        for (int n = tid; n < N_; n += 256) {
            float acc = bias
                + w0 * bvs[n]        + w1 * bvs[512 + n]
                + w2 * bvs[1024 + n] + w3 * bvs[1536 + n]
                + w4 * bvs[2048 + n] + w5 * bvs[2560 + n];
            g_BV[b * H_ * N_ + h * N_ + n] = acc;
        }
    }
}

// ------------------------------- main --------------------------------------
// 16 rows/block, 2 rows/warp, 256 threads, 256 blocks. Shared BF/BV tiles.
__global__ void __launch_bounds__(256) main_kernel(
    const int* __restrict__ batch, const float* __restrict__ Wo,
    const float* __restrict__ bo, float* __restrict__ out)
{
    extern __shared__ float sm[];
    float* Se   = sm;                       // TM*512
    float* Sg   = sm + TM * N_;             // TM*512
    float* tile = sm + 2 * TM * N_;         // 64*TS
    float* Fs   = tile + 64 * TS;           // TM*64
    __shared__ int bsh[TM];

    const int tid = threadIdx.x;
    const int w = tid >> 5, l = tid & 31;
    const int m0 = blockIdx.x * TM;

    if (tid < TM) bsh[tid] = batch[m0 + tid];
    for (int i = tid; i < TM * H_; i += 256) Fs[i] = g_F[m0 * H_ + i];
    __syncthreads();

    const int bmin = bsh[0], bmax = bsh[TM - 1];
    const int r0 = w * 2, r1 = r0 + 1;
    const int b0 = bsh[r0], b1 = bsh[r1];

    // ---------------- pass 1: scores --------------------------------------
    for (int bc = bmin; bc <= bmax; bc++) {
        const float* src = g_BF + bc * (H_ * N_);
        for (int t = 0; t < N_ / NT; t++) {
            __syncthreads();
            for (int i = tid; i < 64 * 32; i += 256) {
                int h = i >> 5, q = i & 31;
                *(float4*)(tile + h * TS + q * 4) =
                    *(const float4*)(src + h * N_ + t * NT + q * 4);
            }
            __syncthreads();
            const bool a0 = (b0 == bc), a1 = (b1 == bc);
            if (!(a0 | a1)) continue;

            // e-half (h 0..31)
            float4 s0 = {0,0,0,0}, s1 = {0,0,0,0};
            #pragma unroll
            for (int h = 0; h < 32; h++) {
                float4 bv = *(const float4*)(tile + h * TS + l * 4);
                float f0 = Fs[r0 * H_ + h], f1 = Fs[r1 * H_ + h];
                s0.x += bv.x * f0; s0.y += bv.y * f0; s0.z += bv.z * f0; s0.w += bv.w * f0;
                s1.x += bv.x * f1; s1.y += bv.y * f1; s1.z += bv.z * f1; s1.w += bv.w * f1;
            }
            if (a0) {
                float4 o = {s0.x*0.125f, s0.y*0.125f, s0.z*0.125f, s0.w*0.125f};
                *(float4*)(Se + r0 * N_ + t * NT + l * 4) = o;
            }
            if (a1) {
                float4 o = {s1.x*0.125f, s1.y*0.125f, s1.z*0.125f, s1.w*0.125f};
                *(float4*)(Se + r1 * N_ + t * NT + l * 4) = o;
            }
            // g-half (h 32..63)
            float4 t0 = {0,0,0,0}, t1 = {0,0,0,0};
            #pragma unroll
            for (int h = 32; h < 64; h++) {
                float4 bv = *(const float4*)(tile + h * TS + l * 4);
                float f0 = Fs[r0 * H_ + h], f1 = Fs[r1 * H_ + h];
                t0.x += bv.x * f0; t0.y += bv.y * f0; t0.z += bv.z * f0; t0.w += bv.w * f0;
                t1.x += bv.x * f1; t1.y += bv.y * f1; t1.z += bv.z * f1; t1.w += bv.w * f1;
            }
            if (a0) {
                float4 o = {t0.x*0.125f, t0.y*0.125f, t0.z*0.125f, t0.w*0.125f};
                *(float4*)(Sg + r0 * N_ + t * NT + l * 4) = o;
            }
            if (a1) {
                float4 o = {t1.x*0.125f, t1.y*0.125f, t1.z*0.125f, t1.w*0.125f};
                *(float4*)(Sg + r1 * N_ + t * NT + l * 4) = o;
            }
        }
    }
    __syncwarp();

    // ---------------- softmax (per warp, own 2 rows) -----------------------
    float me0 = -1e30f, mg0 = -1e30f, me1 = -1e30f, mg1 = -1e30f;
    #pragma unroll
    for (int k = 0; k < 16; k++) {
        int n = l + 32 * k;
        me0 = fmaxf(me0, Se[r0 * N_ + n]); mg0 = fmaxf(mg0, Sg[r0 * N_ + n]);
        me1 = fmaxf(me1, Se[r1 * N_ + n]); mg1 = fmaxf(mg1, Sg[r1 * N_ + n]);
    }
    #pragma unroll
    for (int off = 16; off; off >>= 1) {
        me0 = fmaxf(me0, __shfl_xor_sync(0xffffffffu, me0, off));
        mg0 = fmaxf(mg0, __shfl_xor_sync(0xffffffffu, mg0, off));
        me1 = fmaxf(me1, __shfl_xor_sync(0xffffffffu, me1, off));
        mg1 = fmaxf(mg1, __shfl_xor_sync(0xffffffffu, mg1, off));
    }
    float se0 = 0.f, sg0 = 0.f, se1 = 0.f, sg1 = 0.f;
    #pragma unroll
    for (int k = 0; k < 16; k++) {
        int n = l + 32 * k;
        float e;
        e = __expf(Se[r0 * N_ + n] - me0); Se[r0 * N_ + n] = e; se0 += e;
        e = __expf(Sg[r0 * N_ + n] - mg0); Sg[r0 * N_ + n] = e; sg0 += e;
        e = __expf(Se[r1 * N_ + n] - me1); Se[r1 * N_ + n] = e; se1 += e;
        e = __expf(Sg[r1 * N_ + n] - mg1); Sg[r1 * N_ + n] = e; sg1 += e;
    }
    #pragma unroll
    for (int off = 16; off; off >>= 1) {
        se0 += __shfl_xor_sync(0xffffffffu, se0, off);
        sg0 += __shfl_xor_sync(0xffffffffu, sg0, off);
        se1 += __shfl_xor_sync(0xffffffffu, se1, off);
        sg1 += __shfl_xor_sync(0xffffffffu, sg1, off);
    }
    const float re0 = 1.f / se0, rg0 = 1.f / sg0;
    const float re1 = 1.f / se1, rg1 = 1.f / sg1;
    __syncwarp();

    // ---------------- pass 2: out = BV @ weights ---------------------------
    float e0a=0,e0b=0,g0a=0,g0b=0, e1a=0,e1b=0,g1a=0,g1b=0;
    for (int bc = bmin; bc <= bmax; bc++) {
        const float* src = g_BV + bc * (H_ * N_);
        for (int t = 0; t < N_ / NT; t++) {
            __syncthreads();
            for (int i = tid; i < 64 * 32; i += 256) {
                int h = i >> 5, q = i & 31;
                *(float4*)(tile + h * TS + q * 4) =
                    *(const float4*)(src + h * N_ + t * NT + q * 4);
            }
            __syncthreads();
            const bool a0 = (b0 == bc), a1 = (b1 == bc);
            if (!(a0 | a1)) continue;
            #pragma unroll 8
            for (int q = 0; q < 32; q++) {
                float4 v0 = *(const float4*)(tile + l * TS + q * 4);          // h = l
                float4 v1 = *(const float4*)(tile + (32 + l) * TS + q * 4);   // h = l+32
                if (a0) {
                    float4 we = *(const float4*)(Se + r0 * N_ + t * NT + q * 4);
                    float4 wg = *(const float4*)(Sg + r0 * N_ + t * NT + q * 4);
                    e0a += v0.x*we.x + v0.y*we.y + v0.z*we.z + v0.w*we.w;
                    e0b += v1.x*we.x + v1.y*we.y + v1.z*we.z + v1.w*we.w;
                    g0a += v0.x*wg.x + v0.y*wg.y + v0.z*wg.z + v0.w*wg.w;
                    g0b += v1.x*wg.x + v1.y*wg.y + v1.z*wg.z + v1.w*wg.w;
                }
                if (a1) {
                    float4 we = *(const float4*)(Se + r1 * N_ + t * NT + q * 4);
                    float4 wg = *(const float4*)(Sg + r1 * N_ + t * NT + q * 4);
                    e1a += v0.x*we.x + v0.y*we.y + v0.z*we.z + v0.w*we.w;
                    e1b += v1.x*we.x + v1.y*we.y + v1.z*we.z + v1.w*we.w;
                    g1a += v0.x*wg.x + v0.y*wg.y + v0.z*wg.z + v0.w*wg.w;
                    g1b += v1.x*wg.x + v1.y*wg.y + v1.z*wg.z + v1.w*wg.w;
                }
            }
        }
    }

    // cat into Se[r][0..128): [out_euc(64) | out_geo(64)], normalized
    Se[r0 * N_ + l]      = e0a * re0;  Se[r0 * N_ + 32 + l] = e0b * re0;
    Se[r0 * N_ + 64 + l] = g0a * rg0;  Se[r0 * N_ + 96 + l] = g0b * rg0;
    Se[r1 * N_ + l]      = e1a * re1;  Se[r1 * N_ + 32 + l] = e1b * re1;
    Se[r1 * N_ + 64 + l] = g1a * rg1;  Se[r1 * N_ + 96 + l] = g1b * rg1;
    __syncthreads();

    // ---------------- pass 3: out = cat @ Wo.T + bo ------------------------
    for (int i = tid; i < 64 * 32; i += 256) {
        int j = i >> 5, q = i & 31;
        *(float4*)(tile + j * TS + q * 4) = *(const float4*)(Wo + j * 128 + q * 4);
    }
    __syncthreads();

    float bo0 = bo[l], bo1 = bo[32 + l];
    #pragma unroll
    for (int rr = 0; rr < 2; rr++) {
        int r = r0 + rr;
        float o0 = bo0, o1 = bo1;
        #pragma unroll 8
        for (int q = 0; q < 32; q++) {
            float4 c  = *(const float4*)(Se + r * N_ + q * 4);
            float4 w0 = *(const float4*)(tile + l * TS + q * 4);
            float4 w1 = *(const float4*)(tile + (32 + l) * TS + q * 4);
            o0 += w0.x*c.x + w0.y*c.y + w0.z*c.z + w0.w*c.w;
            o1 += w1.x*c.x + w1.y*c.y + w1.z*c.z + w1.w*c.w;
        }
        out[(m0 + r) * H_ + l]      = o0;
        out[(m0 + r) * H_ + 32 + l] = o1;
    }
}

// ------------------------------ launch -------------------------------------
extern "C" void kernel_launch(void* const* d_in, const int* in_sizes, int n_in,
                              void* d_out, int out_size)
{
    const float* fin  = (const float*)d_in[0];
    const int*   batch= (const int*)  d_in[1];
    const float* bpre = (const float*)d_in[2];
    const float* bvin = (const float*)d_in[3];
    const float* Wf   = (const float*)d_in[4];
    const float* bf   = (const float*)d_in[5];
    const float* Wb   = (const float*)d_in[6];
    const float* bb   = (const float*)d_in[7];
    const float* Wbv  = (const float*)d_in[8];
    const float* bbv  = (const float*)d_in[9];
    const float* Wo   = (const float*)d_in[10];
    const float* bo   = (const float*)d_in[11];
    float* out = (float*)d_out;

    const int smem = (2 * TM * N_ + 64 * TS + TM * H_) * sizeof(float);
    cudaFuncSetAttribute(main_kernel, cudaFuncAttributeMaxDynamicSharedMemorySize, smem);

    prep_f_kernel<<<M_ / 16, 256>>>(fin, Wf, bf);
    prep_bf_kernel<<<B_ * (N_ / 64), 256>>>(bpre, Wb, bb);
    prep_bv_kernel<<<B_ * 8, 256>>>(bvin, Wbv, bbv);
    main_kernel<<<M_ / TM, 256, smem>>>(batch, Wo, bo, out);
}

// round 4
// speedup vs baseline: 2.6123x; 1.0643x over previous
#include <cuda_runtime.h>

#define M_   4096
#define B_   8
#define N_   512
#define FD_  128
#define BD_  128
#define BVD_ 6
#define H_   64
#define TM   16        // rows per block
#define NT   128       // n-tile width
#define TS   132       // tile row stride (words)
#define SES  516       // score row stride (words)

__device__ float g_F[M_ * H_];        // (m, h)
__device__ float g_BF[B_ * H_ * N_];  // (b, h, n)
__device__ float g_BV[B_ * H_ * N_];  // (b, h, n)

// ---------------- fused prep kernel ----------------------------------------
__global__ void __launch_bounds__(256) prep_all_kernel(
    const float* __restrict__ fin, const float* __restrict__ Wf,
    const float* __restrict__ bf,
    const float* __restrict__ bpre, const float* __restrict__ Wb,
    const float* __restrict__ bb,
    const float* __restrict__ bvin, const float* __restrict__ Wbv,
    const float* __restrict__ bbv)
{
    extern __shared__ float psm[];
    const int tid = threadIdx.x;
    const int bid = blockIdx.x;

    if (bid < 256) {
        // ---- F[m][h] = Wf[h] . fin[m] + bf[h] ----
        float* WfT = psm;            // [d][h] stride 65
        float* fsh = psm + 8320;     // [16][128]
        const int m0 = bid * 16;
        for (int i = tid; i < H_ * FD_; i += 256) {
            int h = i >> 7, d = i & 127;
            WfT[d * 65 + h] = Wf[i];
        }
        for (int i = tid; i < 16 * 128; i += 256)
            fsh[i] = fin[m0 * FD_ + i];
        __syncthreads();

        const int h  = tid & 63;
        const int r0 = tid >> 6;
        const float bfh = bf[h];
        for (int rr = 0; rr < 4; rr++) {
            int r = rr * 4 + r0;
            float acc = bfh;
            #pragma unroll 16
            for (int d = 0; d < 128; d++)
                acc += WfT[d * 65 + h] * fsh[r * 128 + d];
            g_F[(m0 + r) * H_ + h] = acc;
        }
    } else if (bid < 320) {
        // ---- BF[b][h][n] = Wb[h] . bpre[b][:][n] + bb[h] ----
        float* Wbs = psm;            // [h][d] 8192
        const int q  = bid - 256;
        const int b  = q >> 3;
        const int n0 = (q & 7) * 64;
        for (int i = tid; i < H_ * BD_; i += 256) Wbs[i] = Wb[i];
        __syncthreads();

        const int n  = tid & 63;
        const int hb = (tid >> 6) * 16;
        const float* src = bpre + b * BD_ * N_ + n0 + n;
        float acc[16];
        #pragma unroll
        for (int hh = 0; hh < 16; hh++) acc[hh] = 0.f;
        for (int d = 0; d < BD_; d++) {
            float v = __ldg(src + d * N_);
            #pragma unroll
            for (int hh = 0; hh < 16; hh++)
                acc[hh] += Wbs[(hb + hh) * BD_ + d] * v;
        }
        #pragma unroll
        for (int hh = 0; hh < 16; hh++)
            g_BF[b * H_ * N_ + (hb + hh) * N_ + n0 + n] = acc[hh] + bb[hb + hh];
    } else {
        // ---- BV[b][h][n] = Wbv[h] . bvin[b][:][n] + bbv[h] ----
        float* bvs = psm;            // [c][n] 3072
        const int q  = bid - 320;
        const int b  = q >> 3;
        const int h0 = (q & 7) * 8;
        for (int i = tid; i < BVD_ * N_; i += 256) bvs[i] = bvin[b * BVD_ * N_ + i];
        __syncthreads();

        #pragma unroll
        for (int hh = 0; hh < 8; hh++) {
            int h = h0 + hh;
            float w0 = __ldg(Wbv + h * 6 + 0), w1 = __ldg(Wbv + h * 6 + 1);
            float w2 = __ldg(Wbv + h * 6 + 2), w3 = __ldg(Wbv + h * 6 + 3);
            float w4 = __ldg(Wbv + h * 6 + 4), w5 = __ldg(Wbv + h * 6 + 5);
            float bias = __ldg(bbv + h);
            for (int n = tid; n < N_; n += 256) {
                float acc = bias
                    + w0 * bvs[n]        + w1 * bvs[512 + n]
                    + w2 * bvs[1024 + n] + w3 * bvs[1536 + n]
                    + w4 * bvs[2048 + n] + w5 * bvs[2560 + n];
                g_BV[b * H_ * N_ + h * N_ + n] = acc;
            }
        }
    }
}

// ------------------------------- main --------------------------------------
// smem layout (words): Se[16*516] | Sg[16*516] | tile[64*132] | Fs[16*64] |
//                      cat[16*128] | nrm[32]
__global__ void __launch_bounds__(256) main_kernel(
    const int* __restrict__ batch, const float* __restrict__ Wo,
    const float* __restrict__ bo, float* __restrict__ out)
{
    extern __shared__ float sm[];
    float* Se   = sm;
    float* Sg   = sm + 8256;
    float* tile = sm + 16512;
    float* Fs   = sm + 24960;
    float* cat  = sm + 25984;
    float* nrm  = sm + 28032;
    __shared__ int bsh[TM];

    const int tid = threadIdx.x;
    const int w = tid >> 5, l = tid & 31;
    const int m0 = blockIdx.x * TM;

    if (tid < TM) bsh[tid] = batch[m0 + tid];
    for (int i = tid; i < TM * H_; i += 256) Fs[i] = g_F[m0 * H_ + i];
    __syncthreads();

    const int bmin = bsh[0], bmax = bsh[TM - 1];
    const bool uniform = (bmin == bmax);

    // =================== pass 1: scores ====================================
    // warp w: half = w&1 (0:e uses h[0,32), 1:g uses h[32,64)), rows rw1..rw1+3
    {
        const int half1 = w & 1;
        const int rw1   = (w >> 1) * 4;
        const float* fr = Fs + rw1 * H_ + half1 * 32;   // fr[j*64 + k]
        float* S = half1 ? Sg : Se;

        for (int bc = bmin; bc <= bmax; bc++) {
            const float* src = g_BF + bc * (H_ * N_);
            for (int t = 0; t < N_ / NT; t++) {
                __syncthreads();
                for (int i = tid; i < 64 * 32; i += 256) {
                    int h = i >> 5, q = i & 31;
                    *(float4*)(tile + h * TS + q * 4) =
                        *(const float4*)(src + h * N_ + t * NT + q * 4);
                }
                __syncthreads();

                float4 a0 = {0,0,0,0}, a1 = {0,0,0,0}, a2 = {0,0,0,0}, a3 = {0,0,0,0};
                const float* tb = tile + half1 * 32 * TS + (l << 2);
                #pragma unroll 8
                for (int k = 0; k < 32; k++) {
                    float4 bv = *(const float4*)(tb + k * TS);
                    float f0 = fr[k], f1 = fr[64 + k], f2 = fr[128 + k], f3 = fr[192 + k];
                    a0.x += bv.x*f0; a0.y += bv.y*f0; a0.z += bv.z*f0; a0.w += bv.w*f0;
                    a1.x += bv.x*f1; a1.y += bv.y*f1; a1.z += bv.z*f1; a1.w += bv.w*f1;
                    a2.x += bv.x*f2; a2.y += bv.y*f2; a2.z += bv.z*f2; a2.w += bv.w*f2;
                    a3.x += bv.x*f3; a3.y += bv.y*f3; a3.z += bv.z*f3; a3.w += bv.w*f3;
                }
                float* dst = S + t * NT + (l << 2);
                if (bsh[rw1 + 0] == bc) {
                    float4 o = {a0.x*0.125f, a0.y*0.125f, a0.z*0.125f, a0.w*0.125f};
                    *(float4*)(dst + (rw1 + 0) * SES) = o;
                }
                if (bsh[rw1 + 1] == bc) {
                    float4 o = {a1.x*0.125f, a1.y*0.125f, a1.z*0.125f, a1.w*0.125f};
                    *(float4*)(dst + (rw1 + 1) * SES) = o;
                }
                if (bsh[rw1 + 2] == bc) {
                    float4 o = {a2.x*0.125f, a2.y*0.125f, a2.z*0.125f, a2.w*0.125f};
                    *(float4*)(dst + (rw1 + 2) * SES) = o;
                }
                if (bsh[rw1 + 3] == bc) {
                    float4 o = {a3.x*0.125f, a3.y*0.125f, a3.z*0.125f, a3.w*0.125f};
                    *(float4*)(dst + (rw1 + 3) * SES) = o;
                }
            }
        }
    }
    __syncthreads();

    // =================== softmax (warp owns rows 2w, 2w+1) =================
    {
        const int r0 = 2 * w, r1 = r0 + 1;
        float me0 = -1e30f, mg0 = -1e30f, me1 = -1e30f, mg1 = -1e30f;
        #pragma unroll
        for (int k = 0; k < 16; k++) {
            int n = l + 32 * k;
            me0 = fmaxf(me0, Se[r0 * SES + n]); mg0 = fmaxf(mg0, Sg[r0 * SES + n]);
            me1 = fmaxf(me1, Se[r1 * SES + n]); mg1 = fmaxf(mg1, Sg[r1 * SES + n]);
        }
        #pragma unroll
        for (int off = 16; off; off >>= 1) {
            me0 = fmaxf(me0, __shfl_xor_sync(0xffffffffu, me0, off));
            mg0 = fmaxf(mg0, __shfl_xor_sync(0xffffffffu, mg0, off));
            me1 = fmaxf(me1, __shfl_xor_sync(0xffffffffu, me1, off));
            mg1 = fmaxf(mg1, __shfl_xor_sync(0xffffffffu, mg1, off));
        }
        float se0 = 0.f, sg0 = 0.f, se1 = 0.f, sg1 = 0.f;
        #pragma unroll
        for (int k = 0; k < 16; k++) {
            int n = l + 32 * k;
            float e;
            e = __expf(Se[r0 * SES + n] - me0); Se[r0 * SES + n] = e; se0 += e;
            e = __expf(Sg[r0 * SES + n] - mg0); Sg[r0 * SES + n] = e; sg0 += e;
            e = __expf(Se[r1 * SES + n] - me1); Se[r1 * SES + n] = e; se1 += e;
            e = __expf(Sg[r1 * SES + n] - mg1); Sg[r1 * SES + n] = e; sg1 += e;
        }
        #pragma unroll
        for (int off = 16; off; off >>= 1) {
            se0 += __shfl_xor_sync(0xffffffffu, se0, off);
            sg0 += __shfl_xor_sync(0xffffffffu, sg0, off);
            se1 += __shfl_xor_sync(0xffffffffu, se1, off);
            sg1 += __shfl_xor_sync(0xffffffffu, sg1, off);
        }
        if (l == 0) {
            nrm[r0] = 1.f / se0;  nrm[r1] = 1.f / se1;
            nrm[16 + r0] = 1.f / sg0;  nrm[16 + r1] = 1.f / sg1;
        }
    }
    __syncthreads();

    // =================== pass 2: out = BV @ weights ========================
    // compute warps w<4: wr=w>>1 (rows wr*8..+8), wc=w&1 (h-block wc*32)
    // lane: lr=l>>3 -> rows rA=rw0+2lr+{0,1}; lc=l&7 -> h = wc*32+lc+8i
    {
        const int wr = w >> 1, wc = w & 1;
        const int rw0 = wr * 8;
        const int lr = l >> 3, lc = l & 7;
        const int rA = rw0 + lr * 2;
        const float* We = Se + rA * SES;
        const float* Wg = Sg + rA * SES;
        const int hb = wc * 32 + lc;

        float cE0[4] = {0,0,0,0}, cE1[4] = {0,0,0,0};
        float cG0[4] = {0,0,0,0}, cG1[4] = {0,0,0,0};

        for (int bc = bmin; bc <= bmax; bc++) {
            const float* src = g_BV + bc * (H_ * N_);
            for (int t = 0; t < N_ / NT; t++) {
                __syncthreads();
                for (int i = tid; i < 64 * 32; i += 256) {
                    int h = i >> 5, q = i & 31;
                    *(float4*)(tile + h * TS + q * 4) =
                        *(const float4*)(src + h * N_ + t * NT + q * 4);
                }
                __syncthreads();
                if (w >= 4) continue;

                const int tb = t * NT;
                if (uniform) {
                    #pragma unroll 4
                    for (int kk = 0; kk < NT; kk += 4) {
                        float4 ae0 = *(const float4*)(We + tb + kk);
                        float4 ae1 = *(const float4*)(We + SES + tb + kk);
                        float4 ag0 = *(const float4*)(Wg + tb + kk);
                        float4 ag1 = *(const float4*)(Wg + SES + tb + kk);
                        float4 b0 = *(const float4*)(tile + (hb     ) * TS + kk);
                        float4 b1 = *(const float4*)(tile + (hb +  8) * TS + kk);
                        float4 b2 = *(const float4*)(tile + (hb + 16) * TS + kk);
                        float4 b3 = *(const float4*)(tile + (hb + 24) * TS + kk);
                        cE0[0] += ae0.x*b0.x + ae0.y*b0.y + ae0.z*b0.z + ae0.w*b0.w;
                        cE0[1] += ae0.x*b1.x + ae0.y*b1.y + ae0.z*b1.z + ae0.w*b1.w;
                        cE0[2] += ae0.x*b2.x + ae0.y*b2.y + ae0.z*b2.z + ae0.w*b2.w;
                        cE0[3] += ae0.x*b3.x + ae0.y*b3.y + ae0.z*b3.z + ae0.w*b3.w;
                        cE1[0] += ae1.x*b0.x + ae1.y*b0.y + ae1.z*b0.z + ae1.w*b0.w;
                        cE1[1] += ae1.x*b1.x + ae1.y*b1.y + ae1.z*b1.z + ae1.w*b1.w;
                        cE1[2] += ae1.x*b2.x + ae1.y*b2.y + ae1.z*b2.z + ae1.w*b2.w;
                        cE1[3] += ae1.x*b3.x + ae1.y*b3.y + ae1.z*b3.z + ae1.w*b3.w;
                        cG0[0] += ag0.x*b0.x + ag0.y*b0.y + ag0.z*b0.z + ag0.w*b0.w;
                        cG0[1] += ag0.x*b1.x + ag0.y*b1.y + ag0.z*b1.z + ag0.w*b1.w;
                        cG0[2] += ag0.x*b2.x + ag0.y*b2.y + ag0.z*b2.z + ag0.w*b2.w;
                        cG0[3] += ag0.x*b3.x + ag0.y*b3.y + ag0.z*b3.z + ag0.w*b3.w;
                        cG1[0] += ag1.x*b0.x + ag1.y*b0.y + ag1.z*b0.z + ag1.w*b0.w;
                        cG1[1] += ag1.x*b1.x + ag1.y*b1.y + ag1.z*b1.z + ag1.w*b1.w;
                        cG1[2] += ag1.x*b2.x + ag1.y*b2.y + ag1.z*b2.z + ag1.w*b2.w;
                        cG1[3] += ag1.x*b3.x + ag1.y*b3.y + ag1.z*b3.z + ag1.w*b3.w;
                    }
                } else {
                    const float m0f = (bsh[rA]     == bc) ? 1.f : 0.f;
                    const float m1f = (bsh[rA + 1] == bc) ? 1.f : 0.f;
                    #pragma unroll 4
                    for (int kk = 0; kk < NT; kk += 4) {
                        float4 ae0 = *(const float4*)(We + tb + kk);
                        float4 ae1 = *(const float4*)(We + SES + tb + kk);
                        float4 ag0 = *(const float4*)(Wg + tb + kk);
                        float4 ag1 = *(const float4*)(Wg + SES + tb + kk);
                        ae0.x *= m0f; ae0.y *= m0f; ae0.z *= m0f; ae0.w *= m0f;
                        ae1.x *= m1f; ae1.y *= m1f; ae1.z *= m1f; ae1.w *= m1f;
                        ag0.x *= m0f; ag0.y *= m0f; ag0.z *= m0f; ag0.w *= m0f;
                        ag1.x *= m1f; ag1.y *= m1f; ag1.z *= m1f; ag1.w *= m1f;
                        float4 b0 = *(const float4*)(tile + (hb     ) * TS + kk);
                        float4 b1 = *(const float4*)(tile + (hb +  8) * TS + kk);
                        float4 b2 = *(const float4*)(tile + (hb + 16) * TS + kk);
                        float4 b3 = *(const float4*)(tile + (hb + 24) * TS + kk);
                        cE0[0] += ae0.x*b0.x + ae0.y*b0.y + ae0.z*b0.z + ae0.w*b0.w;
                        cE0[1] += ae0.x*b1.x + ae0.y*b1.y + ae0.z*b1.z + ae0.w*b1.w;
                        cE0[2] += ae0.x*b2.x + ae0.y*b2.y + ae0.z*b2.z + ae0.w*b2.w;
                        cE0[3] += ae0.x*b3.x + ae0.y*b3.y + ae0.z*b3.z + ae0.w*b3.w;
                        cE1[0] += ae1.x*b0.x + ae1.y*b0.y + ae1.z*b0.z + ae1.w*b0.w;
                        cE1[1] += ae1.x*b1.x + ae1.y*b1.y + ae1.z*b1.z + ae1.w*b1.w;
                        cE1[2] += ae1.x*b2.x + ae1.y*b2.y + ae1.z*b2.z + ae1.w*b2.w;
                        cE1[3] += ae1.x*b3.x + ae1.y*b3.y + ae1.z*b3.z + ae1.w*b3.w;
                        cG0[0] += ag0.x*b0.x + ag0.y*b0.y + ag0.z*b0.z + ag0.w*b0.w;
                        cG0[1] += ag0.x*b1.x + ag0.y*b1.y + ag0.z*b1.z + ag0.w*b1.w;
                        cG0[2] += ag0.x*b2.x + ag0.y*b2.y + ag0.z*b2.z + ag0.w*b2.w;
                        cG0[3] += ag0.x*b3.x + ag0.y*b3.y + ag0.z*b3.z + ag0.w*b3.w;
                        cG1[0] += ag1.x*b0.x + ag1.y*b0.y + ag1.z*b0.z + ag1.w*b0.w;
                        cG1[1] += ag1.x*b1.x + ag1.y*b1.y + ag1.z*b1.z + ag1.w*b1.w;
                        cG1[2] += ag1.x*b2.x + ag1.y*b2.y + ag1.z*b2.z + ag1.w*b2.w;
                        cG1[3] += ag1.x*b3.x + ag1.y*b3.y + ag1.z*b3.z + ag1.w*b3.w;
                    }
                }
            }
        }

        if (w < 4) {
            const float nE0 = nrm[rA], nE1 = nrm[rA + 1];
            const float nG0 = nrm[16 + rA], nG1 = nrm[16 + rA + 1];
            #pragma unroll
            for (int i = 0; i < 4; i++) {
                int ho = wc * 32 + lc + 8 * i;
                cat[rA * 128 + ho]            = cE0[i] * nE0;
                cat[(rA + 1) * 128 + ho]      = cE1[i] * nE1;
                cat[rA * 128 + 64 + ho]       = cG0[i] * nG0;
                cat[(rA + 1) * 128 + 64 + ho] = cG1[i] * nG1;
            }
        }
    }
    __syncthreads();

    // =================== pass 3: out = cat @ Wo.T + bo =====================
    for (int i = tid; i < 64 * 32; i += 256) {
        int j = i >> 5, q = i & 31;
        *(float4*)(tile + j * TS + q * 4) = *(const float4*)(Wo + j * 128 + q * 4);
    }
    __syncthreads();

    {
        const int r0 = 2 * w;
        const float bo0 = bo[l], bo1 = bo[32 + l];
        #pragma unroll
        for (int rr = 0; rr < 2; rr++) {
            int r = r0 + rr;
            float o0 = bo0, o1 = bo1;
            #pragma unroll 8
            for (int q = 0; q < 32; q++) {
                float4 c  = *(const float4*)(cat + r * 128 + q * 4);
                float4 w0 = *(const float4*)(tile + l * TS + q * 4);
                float4 w1 = *(const float4*)(tile + (32 + l) * TS + q * 4);
                o0 += w0.x*c.x + w0.y*c.y + w0.z*c.z + w0.w*c.w;
                o1 += w1.x*c.x + w1.y*c.y + w1.z*c.z + w1.w*c.w;
            }
            out[(m0 + r) * H_ + l]      = o0;
            out[(m0 + r) * H_ + 32 + l] = o1;
        }
    }
}

// ------------------------------ launch -------------------------------------
extern "C" void kernel_launch(void* const* d_in, const int* in_sizes, int n_in,
                              void* d_out, int out_size)
{
    const float* fin  = (const float*)d_in[0];
    const int*   batch= (const int*)  d_in[1];
    const float* bpre = (const float*)d_in[2];
    const float* bvin = (const float*)d_in[3];
    const float* Wf   = (const float*)d_in[4];
    const float* bf   = (const float*)d_in[5];
    const float* Wb   = (const float*)d_in[6];
    const float* bb   = (const float*)d_in[7];
    const float* Wbv  = (const float*)d_in[8];
    const float* bbv  = (const float*)d_in[9];
    const float* Wo   = (const float*)d_in[10];
    const float* bo   = (const float*)d_in[11];
    float* out = (float*)d_out;

    const int psm  = 10368 * sizeof(float);   // 41.5 KB (< 48 KB default)
    const int msm  = 28064 * sizeof(float);   // 112.25 KB
    cudaFuncSetAttribute(main_kernel, cudaFuncAttributeMaxDynamicSharedMemorySize, msm);

    prep_all_kernel<<<384, 256, psm>>>(fin, Wf, bf, bpre, Wb, bb, bvin, Wbv, bbv);
    main_kernel<<<M_ / TM, 256, msm>>>(batch, Wo, bo, out);
}

// round 5
// speedup vs baseline: 3.0028x; 1.1495x over previous
#include <cuda_runtime.h>

#define M_   4096
#define B_   8
#define N_   512
#define FD_  128
#define BD_  128
#define BVD_ 6
#define H_   64
#define TM   16        // rows per block
#define NT   128       // n-tile width
#define TS   132       // tile row stride (words)
#define SES  516       // score row stride (words)

__device__ float g_F[M_ * H_];        // (m, h)
__device__ float g_BF[B_ * H_ * N_];  // (b, h, n)
__device__ float g_BV[B_ * H_ * N_];  // (b, h, n)

// ---- packed fp32x2 FMA (Blackwell FFMA2; ptxas never emits it from C++) ----
__device__ __forceinline__ void fma2(float2& d, const float2 a, const float2 b) {
    unsigned long long& dd = *reinterpret_cast<unsigned long long*>(&d);
    const unsigned long long aa = *reinterpret_cast<const unsigned long long*>(&a);
    const unsigned long long bb = *reinterpret_cast<const unsigned long long*>(&b);
    asm("fma.rn.f32x2 %0, %1, %2, %0;" : "+l"(dd) : "l"(aa), "l"(bb));
}
__device__ __forceinline__ float2 dup(float s) { return make_float2(s, s); }

// ---------------- fused prep kernel ----------------------------------------
// bid 0..63   : F    (64 rows each)
// bid 64..127 : BF   (b = q>>3, n-chunk of 64)
// bid 128..135: BV   (one batch each)
__global__ void __launch_bounds__(256) prep_all_kernel(
    const float* __restrict__ fin, const float* __restrict__ Wf,
    const float* __restrict__ bf,
    const float* __restrict__ bpre, const float* __restrict__ Wb,
    const float* __restrict__ bb,
    const float* __restrict__ bvin, const float* __restrict__ Wbv,
    const float* __restrict__ bbv)
{
    extern __shared__ float psm[];
    const int tid = threadIdx.x;
    const int bid = blockIdx.x;

    if (bid < 64) {
        // ---- F[m][h] = Wf[h] . fin[m] + bf[h], 64 rows/block ----
        float* WfT = psm;           // [d][h] stride 68
        float* FnT = psm + 8704;    // [d][r] stride 68
        const int m0 = bid * 64;
        for (int i = tid; i < 64 * 128; i += 256) {
            int h = i >> 7, d = i & 127;
            WfT[d * 68 + h] = Wf[i];
            FnT[d * 68 + h] = fin[(m0 + h) * FD_ + d];   // h reused as row idx
        }
        __syncthreads();

        const int h0 = (tid & 15) * 4;
        const int r0 = (tid >> 4) * 4;
        float2 acc[4][2];
        #pragma unroll
        for (int i = 0; i < 4; i++) { acc[i][0] = dup(0.f); acc[i][1] = dup(0.f); }

        #pragma unroll 4
        for (int d = 0; d < 128; d++) {
            float4 w4 = *(const float4*)(WfT + d * 68 + h0);
            float4 f4 = *(const float4*)(FnT + d * 68 + r0);
            float2 wl = make_float2(w4.x, w4.y), wh = make_float2(w4.z, w4.w);
            fma2(acc[0][0], wl, dup(f4.x)); fma2(acc[0][1], wh, dup(f4.x));
            fma2(acc[1][0], wl, dup(f4.y)); fma2(acc[1][1], wh, dup(f4.y));
            fma2(acc[2][0], wl, dup(f4.z)); fma2(acc[2][1], wh, dup(f4.z));
            fma2(acc[3][0], wl, dup(f4.w)); fma2(acc[3][1], wh, dup(f4.w));
        }
        float4 bf4 = *(const float4*)(bf + h0);
        #pragma unroll
        for (int ri = 0; ri < 4; ri++) {
            float4 o = make_float4(acc[ri][0].x + bf4.x, acc[ri][0].y + bf4.y,
                                   acc[ri][1].x + bf4.z, acc[ri][1].y + bf4.w);
            *(float4*)(g_F + (m0 + r0 + ri) * H_ + h0) = o;
        }
    } else if (bid < 128) {
        // ---- BF[b][h][n] = Wb[h] . bpre[b][:][n] + bb[h] ----
        float* WbT = psm;           // [d][h] stride 68
        float* bp  = psm + 8704;    // [d][nn] stride 64
        const int q  = bid - 64;
        const int b  = q >> 3;
        const int n0 = (q & 7) * 64;

        for (int i = tid; i < 64 * 128; i += 256) {
            int h = i >> 7, d = i & 127;
            WbT[d * 68 + h] = Wb[i];
        }
        for (int i = tid; i < 2048; i += 256) {
            int d = i >> 4, nn4 = (i & 15) << 2;
            *(float4*)(bp + d * 64 + nn4) =
                *(const float4*)(bpre + b * BD_ * N_ + d * N_ + n0 + nn4);
        }
        __syncthreads();

        const int h0  = (tid & 15) * 4;
        const int nn0 = (tid >> 4) * 4;
        float2 acc[4][2];
        #pragma unroll
        for (int i = 0; i < 4; i++) { acc[i][0] = dup(0.f); acc[i][1] = dup(0.f); }

        #pragma unroll 4
        for (int d = 0; d < 128; d++) {
            float4 w4 = *(const float4*)(WbT + d * 68 + h0);
            float4 v4 = *(const float4*)(bp + d * 64 + nn0);
            float2 vl = make_float2(v4.x, v4.y), vh = make_float2(v4.z, v4.w);
            fma2(acc[0][0], vl, dup(w4.x)); fma2(acc[0][1], vh, dup(w4.x));
            fma2(acc[1][0], vl, dup(w4.y)); fma2(acc[1][1], vh, dup(w4.y));
            fma2(acc[2][0], vl, dup(w4.z)); fma2(acc[2][1], vh, dup(w4.z));
            fma2(acc[3][0], vl, dup(w4.w)); fma2(acc[3][1], vh, dup(w4.w));
        }
        #pragma unroll
        for (int hi = 0; hi < 4; hi++) {
            float bbh = __ldg(bb + h0 + hi);
            float4 o = make_float4(acc[hi][0].x + bbh, acc[hi][0].y + bbh,
                                   acc[hi][1].x + bbh, acc[hi][1].y + bbh);
            *(float4*)(g_BF + b * H_ * N_ + (h0 + hi) * N_ + n0 + nn0) = o;
        }
    } else {
        // ---- BV[b][h][n] = Wbv[h] . bvin[b][:][n] + bbv[h] ----
        float* bvs = psm;           // [c][n] 3072 words
        const int b = bid - 128;
        for (int i = tid; i < BVD_ * N_; i += 256) bvs[i] = bvin[b * BVD_ * N_ + i];
        __syncthreads();

        for (int h = 0; h < H_; h++) {
            float w0 = __ldg(Wbv + h * 6 + 0), w1 = __ldg(Wbv + h * 6 + 1);
            float w2 = __ldg(Wbv + h * 6 + 2), w3 = __ldg(Wbv + h * 6 + 3);
            float w4 = __ldg(Wbv + h * 6 + 4), w5 = __ldg(Wbv + h * 6 + 5);
            float bias = __ldg(bbv + h);
            for (int n = tid; n < N_; n += 256) {
                float acc = bias
                    + w0 * bvs[n]        + w1 * bvs[512 + n]
                    + w2 * bvs[1024 + n] + w3 * bvs[1536 + n]
                    + w4 * bvs[2048 + n] + w5 * bvs[2560 + n];
                g_BV[b * H_ * N_ + h * N_ + n] = acc;
            }
        }
    }
}

// ------------------------------- main --------------------------------------
__global__ void __launch_bounds__(256) main_kernel(
    const int* __restrict__ batch, const float* __restrict__ Wo,
    const float* __restrict__ bo, float* __restrict__ out)
{
    extern __shared__ float sm[];
    float* Se   = sm;            // 16*516
    float* Sg   = sm + 8256;     // 16*516
    float* tile = sm + 16512;    // 64*132
    float* Fs   = sm + 24960;    // 16*64
    float* cat  = sm + 25984;    // 16*128
    float* nrm  = sm + 28032;    // 32
    __shared__ int bsh[TM];

    const int tid = threadIdx.x;
    const int w = tid >> 5, l = tid & 31;
    const int m0 = blockIdx.x * TM;

    if (tid < TM) bsh[tid] = batch[m0 + tid];
    for (int i = tid; i < TM * H_; i += 256) Fs[i] = g_F[m0 * H_ + i];
    __syncthreads();

    const int bmin = bsh[0], bmax = bsh[TM - 1];
    const int nb = bmax - bmin + 1;
    const int ntile = nb * 4;

    float4 pf[8];

    // prefetch BF tile 0
    {
        const float* sp = g_BF + bmin * (H_ * N_);
        #pragma unroll
        for (int s = 0; s < 8; s++) {
            int j = tid + (s << 8); int h = j >> 5; int q = j & 31;
            pf[s] = *(const float4*)(sp + h * N_ + q * 4);
        }
    }

    // =================== pass 1: scores ====================================
    {
        const int half1 = w & 1;
        const int rw1   = (w >> 1) * 4;
        const float* fr = Fs + rw1 * H_ + half1 * 32;
        float* S = half1 ? Sg : Se;

        for (int it = 0; it < ntile; it++) {
            __syncthreads();
            #pragma unroll
            for (int s = 0; s < 8; s++) {
                int j = tid + (s << 8); int h = j >> 5; int q = j & 31;
                *(float4*)(tile + h * TS + q * 4) = pf[s];
            }
            if (it + 1 < ntile) {
                const float* sp = g_BF + (bmin + ((it + 1) >> 2)) * (H_ * N_)
                                       + ((it + 1) & 3) * NT;
                #pragma unroll
                for (int s = 0; s < 8; s++) {
                    int j = tid + (s << 8); int h = j >> 5; int q = j & 31;
                    pf[s] = *(const float4*)(sp + h * N_ + q * 4);
                }
            }
            __syncthreads();

            const int bc = bmin + (it >> 2), t = it & 3;
            float2 a0l = dup(0.f), a0h = dup(0.f), a1l = dup(0.f), a1h = dup(0.f);
            float2 a2l = dup(0.f), a2h = dup(0.f), a3l = dup(0.f), a3h = dup(0.f);
            const float* tb = tile + half1 * 32 * TS + (l << 2);

            #pragma unroll
            for (int k4 = 0; k4 < 32; k4 += 4) {
                float4 f0 = *(const float4*)(fr + k4);
                float4 f1 = *(const float4*)(fr + 64 + k4);
                float4 f2 = *(const float4*)(fr + 128 + k4);
                float4 f3 = *(const float4*)(fr + 192 + k4);
                const float* fp0 = (const float*)&f0;
                const float* fp1 = (const float*)&f1;
                const float* fp2 = (const float*)&f2;
                const float* fp3 = (const float*)&f3;
                #pragma unroll
                for (int kk = 0; kk < 4; kk++) {
                    float4 bv = *(const float4*)(tb + (k4 + kk) * TS);
                    float2 bl = make_float2(bv.x, bv.y);
                    float2 bh = make_float2(bv.z, bv.w);
                    fma2(a0l, bl, dup(fp0[kk])); fma2(a0h, bh, dup(fp0[kk]));
                    fma2(a1l, bl, dup(fp1[kk])); fma2(a1h, bh, dup(fp1[kk]));
                    fma2(a2l, bl, dup(fp2[kk])); fma2(a2h, bh, dup(fp2[kk]));
                    fma2(a3l, bl, dup(fp3[kk])); fma2(a3h, bh, dup(fp3[kk]));
                }
            }
            float* dst = S + t * NT + (l << 2);
            if (bsh[rw1 + 0] == bc) {
                float4 o = make_float4(a0l.x*0.125f, a0l.y*0.125f, a0h.x*0.125f, a0h.y*0.125f);
                *(float4*)(dst + (rw1 + 0) * SES) = o;
            }
            if (bsh[rw1 + 1] == bc) {
                float4 o = make_float4(a1l.x*0.125f, a1l.y*0.125f, a1h.x*0.125f, a1h.y*0.125f);
                *(float4*)(dst + (rw1 + 1) * SES) = o;
            }
            if (bsh[rw1 + 2] == bc) {
                float4 o = make_float4(a2l.x*0.125f, a2l.y*0.125f, a2h.x*0.125f, a2h.y*0.125f);
                *(float4*)(dst + (rw1 + 2) * SES) = o;
            }
            if (bsh[rw1 + 3] == bc) {
                float4 o = make_float4(a3l.x*0.125f, a3l.y*0.125f, a3h.x*0.125f, a3h.y*0.125f);
                *(float4*)(dst + (rw1 + 3) * SES) = o;
            }
        }
    }
    __syncthreads();

    // prefetch BV tile 0 (overlaps softmax)
    {
        const float* sp = g_BV + bmin * (H_ * N_);
        #pragma unroll
        for (int s = 0; s < 8; s++) {
            int j = tid + (s << 8); int h = j >> 5; int q = j & 31;
            pf[s] = *(const float4*)(sp + h * N_ + q * 4);
        }
    }

    // =================== softmax (warp owns rows 2w, 2w+1) =================
    {
        const int r0 = 2 * w, r1 = r0 + 1;
        float me0 = -1e30f, mg0 = -1e30f, me1 = -1e30f, mg1 = -1e30f;
        #pragma unroll
        for (int k = 0; k < 16; k++) {
            int n = l + 32 * k;
            me0 = fmaxf(me0, Se[r0 * SES + n]); mg0 = fmaxf(mg0, Sg[r0 * SES + n]);
            me1 = fmaxf(me1, Se[r1 * SES + n]); mg1 = fmaxf(mg1, Sg[r1 * SES + n]);
        }
        #pragma unroll
        for (int off = 16; off; off >>= 1) {
            me0 = fmaxf(me0, __shfl_xor_sync(0xffffffffu, me0, off));
            mg0 = fmaxf(mg0, __shfl_xor_sync(0xffffffffu, mg0, off));
            me1 = fmaxf(me1, __shfl_xor_sync(0xffffffffu, me1, off));
            mg1 = fmaxf(mg1, __shfl_xor_sync(0xffffffffu, mg1, off));
        }
        float se0 = 0.f, sg0 = 0.f, se1 = 0.f, sg1 = 0.f;
        #pragma unroll
        for (int k = 0; k < 16; k++) {
            int n = l + 32 * k;
            float e;
            e = __expf(Se[r0 * SES + n] - me0); Se[r0 * SES + n] = e; se0 += e;
            e = __expf(Sg[r0 * SES + n] - mg0); Sg[r0 * SES + n] = e; sg0 += e;
            e = __expf(Se[r1 * SES + n] - me1); Se[r1 * SES + n] = e; se1 += e;
            e = __expf(Sg[r1 * SES + n] - mg1); Sg[r1 * SES + n] = e; sg1 += e;
        }
        #pragma unroll
        for (int off = 16; off; off >>= 1) {
            se0 += __shfl_xor_sync(0xffffffffu, se0, off);
            sg0 += __shfl_xor_sync(0xffffffffu, sg0, off);
            se1 += __shfl_xor_sync(0xffffffffu, se1, off);
            sg1 += __shfl_xor_sync(0xffffffffu, sg1, off);
        }
        if (l == 0) {
            nrm[r0] = 1.f / se0;       nrm[r1] = 1.f / se1;
            nrm[16 + r0] = 1.f / sg0;  nrm[16 + r1] = 1.f / sg1;
        }
    }
    __syncthreads();

    // =================== pass 2: out = BV @ weights (all 8 warps) ==========
    {
        const int wc = w & 1, wr = w >> 1;
        const int lr = l >> 3, lc = l & 7;
        const int row = wr * 4 + lr;           // per-lane row
        const int hb  = wc * 32 + lc;          // h = hb + 8*i
        const float* We = Se + row * SES;
        const float* Wg = Sg + row * SES;
        const int myb = bsh[row];

        float2 e0 = dup(0.f), e1 = dup(0.f), e2 = dup(0.f), e3 = dup(0.f);
        float2 q0 = dup(0.f), q1 = dup(0.f), q2 = dup(0.f), q3 = dup(0.f);

        for (int it = 0; it < ntile; it++) {
            __syncthreads();
            #pragma unroll
            for (int s = 0; s < 8; s++) {
                int j = tid + (s << 8); int h = j >> 5; int q = j & 31;
                *(float4*)(tile + h * TS + q * 4) = pf[s];
            }
            if (it + 1 < ntile) {
                const float* sp = g_BV + (bmin + ((it + 1) >> 2)) * (H_ * N_)
                                       + ((it + 1) & 3) * NT;
                #pragma unroll
                for (int s = 0; s < 8; s++) {
                    int j = tid + (s << 8); int h = j >> 5; int q = j & 31;
                    pf[s] = *(const float4*)(sp + h * N_ + q * 4);
                }
            }
            __syncthreads();

            const int bc = bmin + (it >> 2);
            const int tb = (it & 3) * NT;
            if (myb == bc) {
                #pragma unroll 8
                for (int kk = 0; kk < NT; kk += 4) {
                    float4 ae = *(const float4*)(We + tb + kk);
                    float4 ag = *(const float4*)(Wg + tb + kk);
                    float4 b0 = *(const float4*)(tile + hb * TS + kk);
                    float4 b1 = *(const float4*)(tile + (hb + 8) * TS + kk);
                    float4 b2 = *(const float4*)(tile + (hb + 16) * TS + kk);
                    float4 b3 = *(const float4*)(tile + (hb + 24) * TS + kk);
                    float2 ael = make_float2(ae.x, ae.y), aeh = make_float2(ae.z, ae.w);
                    float2 agl = make_float2(ag.x, ag.y), agh = make_float2(ag.z, ag.w);
                    fma2(e0, make_float2(b0.x, b0.y), ael); fma2(e0, make_float2(b0.z, b0.w), aeh);
                    fma2(e1, make_float2(b1.x, b1.y), ael); fma2(e1, make_float2(b1.z, b1.w), aeh);
                    fma2(e2, make_float2(b2.x, b2.y), ael); fma2(e2, make_float2(b2.z, b2.w), aeh);
                    fma2(e3, make_float2(b3.x, b3.y), ael); fma2(e3, make_float2(b3.z, b3.w), aeh);
                    fma2(q0, make_float2(b0.x, b0.y), agl); fma2(q0, make_float2(b0.z, b0.w), agh);
                    fma2(q1, make_float2(b1.x, b1.y), agl); fma2(q1, make_float2(b1.z, b1.w), agh);
                    fma2(q2, make_float2(b2.x, b2.y), agl); fma2(q2, make_float2(b2.z, b2.w), agh);
                    fma2(q3, make_float2(b3.x, b3.y), agl); fma2(q3, make_float2(b3.z, b3.w), agh);
                }
            }
        }

        const float nE = nrm[row], nG = nrm[16 + row];
        cat[row * 128 + hb]           = (e0.x + e0.y) * nE;
        cat[row * 128 + hb + 8]       = (e1.x + e1.y) * nE;
        cat[row * 128 + hb + 16]      = (e2.x + e2.y) * nE;
        cat[row * 128 + hb + 24]      = (e3.x + e3.y) * nE;
        cat[row * 128 + 64 + hb]      = (q0.x + q0.y) * nG;
        cat[row * 128 + 64 + hb + 8]  = (q1.x + q1.y) * nG;
        cat[row * 128 + 64 + hb + 16] = (q2.x + q2.y) * nG;
        cat[row * 128 + 64 + hb + 24] = (q3.x + q3.y) * nG;
    }
    __syncthreads();

    // =================== pass 3: out = cat @ Wo.T + bo =====================
    for (int i = tid; i < 64 * 32; i += 256) {
        int j = i >> 5, q = i & 31;
        *(float4*)(tile + j * TS + q * 4) = *(const float4*)(Wo + j * 128 + q * 4);
    }
    __syncthreads();

    {
        const int r0 = 2 * w;
        const float bo0 = bo[l], bo1 = bo[32 + l];
        #pragma unroll
        for (int rr = 0; rr < 2; rr++) {
            int r = r0 + rr;
            float2 o0p = dup(0.f), o1p = dup(0.f);
            #pragma unroll 8
            for (int q = 0; q < 32; q++) {
                float4 c  = *(const float4*)(cat + r * 128 + q * 4);
                float4 w0 = *(const float4*)(tile + l * TS + q * 4);
                float4 w1 = *(const float4*)(tile + (32 + l) * TS + q * 4);
                fma2(o0p, make_float2(w0.x, w0.y), make_float2(c.x, c.y));
                fma2(o0p, make_float2(w0.z, w0.w), make_float2(c.z, c.w));
                fma2(o1p, make_float2(w1.x, w1.y), make_float2(c.x, c.y));
                fma2(o1p, make_float2(w1.z, w1.w), make_float2(c.z, c.w));
            }
            out[(m0 + r) * H_ + l]      = bo0 + o0p.x + o0p.y;
            out[(m0 + r) * H_ + 32 + l] = bo1 + o1p.x + o1p.y;
        }
    }
}

// ------------------------------ launch -------------------------------------
extern "C" void kernel_launch(void* const* d_in, const int* in_sizes, int n_in,
                              void* d_out, int out_size)
{
    const float* fin  = (const float*)d_in[0];
    const int*   batch= (const int*)  d_in[1];
    const float* bpre = (const float*)d_in[2];
    const float* bvin = (const float*)d_in[3];
    const float* Wf   = (const float*)d_in[4];
    const float* bf   = (const float*)d_in[5];
    const float* Wb   = (const float*)d_in[6];
    const float* bb   = (const float*)d_in[7];
    const float* Wbv  = (const float*)d_in[8];
    const float* bbv  = (const float*)d_in[9];
    const float* Wo   = (const float*)d_in[10];
    const float* bo   = (const float*)d_in[11];
    float* out = (float*)d_out;

    const int psm = 17408 * sizeof(float);    // 69.6 KB
    const int msm = 28064 * sizeof(float);    // 112.25 KB
    cudaFuncSetAttribute(prep_all_kernel, cudaFuncAttributeMaxDynamicSharedMemorySize, psm);
    cudaFuncSetAttribute(main_kernel, cudaFuncAttributeMaxDynamicSharedMemorySize, msm);

    prep_all_kernel<<<136, 256, psm>>>(fin, Wf, bf, bpre, Wb, bb, bvin, Wbv, bbv);
    main_kernel<<<M_ / TM, 256, msm>>>(batch, Wo, bo, out);
}

// round 7
// speedup vs baseline: 5.2118x; 1.7356x over previous
#include <cuda_runtime.h>
#include <cstdint>

#define M_   4096
#define B_   8
#define N_   512
#define FD_  128
#define BD_  128
#define H_   64
#define TMR  32        // rows per main block
#define NTHR 512

__device__ float g_F[M_ * H_];        // (m, h)
__device__ float g_BF[B_ * H_ * N_];  // (b, h, n)

// ---- packed fp32x2 FMA ----
__device__ __forceinline__ void fma2(float2& d, const float2 a, const float2 b) {
    unsigned long long& dd = *reinterpret_cast<unsigned long long*>(&d);
    const unsigned long long aa = *reinterpret_cast<const unsigned long long*>(&a);
    const unsigned long long bb = *reinterpret_cast<const unsigned long long*>(&b);
    asm("fma.rn.f32x2 %0, %1, %2, %0;" : "+l"(dd) : "l"(aa), "l"(bb));
}
__device__ __forceinline__ float2 dup(float s) { return make_float2(s, s); }

__device__ __forceinline__ uint32_t saddr(const void* p) {
    return (uint32_t)__cvta_generic_to_shared(p);
}
__device__ __forceinline__ void cp16(uint32_t dst, const void* src) {
    asm volatile("cp.async.cg.shared.global [%0], [%1], 16;" :: "r"(dst), "l"(src));
}
#define CP_COMMIT() asm volatile("cp.async.commit_group;")
#define CP_WAIT2()  asm volatile("cp.async.wait_group 2;")

// ---------------- fused prep kernel (F + BF) -------------------------------
__global__ void __launch_bounds__(256) prep_all_kernel(
    const float* __restrict__ fin, const float* __restrict__ Wf,
    const float* __restrict__ bf,
    const float* __restrict__ bpre, const float* __restrict__ Wb,
    const float* __restrict__ bb)
{
    extern __shared__ float psm[];
    const int tid = threadIdx.x;
    const int bid = blockIdx.x;

    if (bid < 64) {
        // ---- F[m][h] = Wf[h] . fin[m] + bf[h], 64 rows/block ----
        float* WfT = psm;           // [d][h] stride 68
        float* FnT = psm + 8704;    // [d][r] stride 68
        const int m0 = bid * 64;
        for (int i = tid; i < 64 * 128; i += 256) {
            int h = i >> 7, d = i & 127;
            WfT[d * 68 + h] = Wf[i];
            FnT[d * 68 + h] = fin[(m0 + h) * FD_ + d];
        }
        __syncthreads();

        const int h0 = (tid & 15) * 4;
        const int r0 = (tid >> 4) * 4;
        float2 acc[4][2];
        #pragma unroll
        for (int i = 0; i < 4; i++) { acc[i][0] = dup(0.f); acc[i][1] = dup(0.f); }

        #pragma unroll 4
        for (int d = 0; d < 128; d++) {
            float4 w4 = *(const float4*)(WfT + d * 68 + h0);
            float4 f4 = *(const float4*)(FnT + d * 68 + r0);
            float2 wl = make_float2(w4.x, w4.y), wh = make_float2(w4.z, w4.w);
            fma2(acc[0][0], wl, dup(f4.x)); fma2(acc[0][1], wh, dup(f4.x));
            fma2(acc[1][0], wl, dup(f4.y)); fma2(acc[1][1], wh, dup(f4.y));
            fma2(acc[2][0], wl, dup(f4.z)); fma2(acc[2][1], wh, dup(f4.z));
            fma2(acc[3][0], wl, dup(f4.w)); fma2(acc[3][1], wh, dup(f4.w));
        }
        float4 bf4 = *(const float4*)(bf + h0);
        #pragma unroll
        for (int ri = 0; ri < 4; ri++) {
            float4 o = make_float4(acc[ri][0].x + bf4.x, acc[ri][0].y + bf4.y,
                                   acc[ri][1].x + bf4.z, acc[ri][1].y + bf4.w);
            *(float4*)(g_F + (m0 + r0 + ri) * H_ + h0) = o;
        }
    } else {
        // ---- BF[b][h][n] = Wb[h] . bpre[b][:][n] + bb[h] ----
        float* WbT = psm;           // [d][h] stride 68
        float* bp  = psm + 8704;    // [d][nn] stride 64
        const int q  = bid - 64;
        const int b  = q >> 3;
        const int n0 = (q & 7) * 64;

        for (int i = tid; i < 64 * 128; i += 256) {
            int h = i >> 7, d = i & 127;
            WbT[d * 68 + h] = Wb[i];
        }
        for (int i = tid; i < 2048; i += 256) {
            int d = i >> 4, nn4 = (i & 15) << 2;
            *(float4*)(bp + d * 64 + nn4) =
                *(const float4*)(bpre + b * BD_ * N_ + d * N_ + n0 + nn4);
        }
        __syncthreads();

        const int h0  = (tid & 15) * 4;
        const int nn0 = (tid >> 4) * 4;
        float2 acc[4][2];
        #pragma unroll
        for (int i = 0; i < 4; i++) { acc[i][0] = dup(0.f); acc[i][1] = dup(0.f); }

        #pragma unroll 4
        for (int d = 0; d < 128; d++) {
            float4 w4 = *(const float4*)(WbT + d * 68 + h0);
            float4 v4 = *(const float4*)(bp + d * 64 + nn0);
            float2 vl = make_float2(v4.x, v4.y), vh = make_float2(v4.z, v4.w);
            fma2(acc[0][0], vl, dup(w4.x)); fma2(acc[0][1], vh, dup(w4.x));
            fma2(acc[1][0], vl, dup(w4.y)); fma2(acc[1][1], vh, dup(w4.y));
            fma2(acc[2][0], vl, dup(w4.z)); fma2(acc[2][1], vh, dup(w4.z));
            fma2(acc[3][0], vl, dup(w4.w)); fma2(acc[3][1], vh, dup(w4.w));
        }
        #pragma unroll
        for (int hi = 0; hi < 4; hi++) {
            float bbh = __ldg(bb + h0 + hi);
            float4 o = make_float4(acc[hi][0].x + bbh, acc[hi][0].y + bbh,
                                   acc[hi][1].x + bbh, acc[hi][1].y + bbh);
            *(float4*)(g_BF + b * H_ * N_ + (h0 + hi) * N_ + n0 + nn0) = o;
        }
    }
}

// ---------------- chunk loader (cp.async) ----------------------------------
__device__ __forceinline__ void issue_chunk(float* bufbase, const float* gb,
                                            int step, int tid) {
    const int k0 = (step & 3) * 8;
    float* db = bufbase + (step & 3) * 8320;
    #pragma unroll
    for (int s = 0; s < 4; s++) {
        int idx = tid + s * 512;
        int row = idx >> 7, col = (idx & 127) * 4;
        int hsrc = (row < 8) ? (k0 + row) : (32 + k0 + row - 8);
        cp16(saddr(db + row * 520 + col), gb + hsrc * 512 + col);
    }
    CP_COMMIT();
}

// ------------------------------- main --------------------------------------
// 32 rows/block, 512 threads, 128 blocks (single wave, 1 block/SM).
// smem (floats): buf[4][16][520]=33280 | bvs 3*520 | Fk 2048 | FkM 2048 |
//                red 512 | fin 64 | rinv 64 | ypart 3072 | yfin 384
// cat (32*132) and WoT (128*68) alias onto buf after pass 1.
__global__ void __launch_bounds__(NTHR) main_kernel(
    const int* __restrict__ batch, const float* __restrict__ bvin,
    const float* __restrict__ Wbv, const float* __restrict__ bbv,
    const float* __restrict__ Wo, const float* __restrict__ bo,
    float* __restrict__ out)
{
    extern __shared__ float sm[];
    float* buf   = sm;            // 33280
    float* cat   = sm;            // alias: 32*132 = 4224
    float* WoT   = sm + 4224;     // alias: 128*68 = 8704
    float* bvs   = sm + 33280;    // 1560
    float* Fk    = sm + 34840;    // 2048  [half][k][r]
    float* FkM   = sm + 36888;    // 2048
    float* red   = sm + 38936;    // 512   [half][warp8][r]
    float* fin   = sm + 39448;    // 64
    float* rinv  = sm + 39512;    // 64
    float* ypart = sm + 39576;    // 3072  [half][warp8][r][6]
    float* yfin  = sm + 42648;    // 384   [half*32+r][6]
    __shared__ int bsh[TMR];

    const int tid = threadIdx.x;
    const int w = tid >> 5, l = tid & 31;
    const int m0 = blockIdx.x * TMR;

    if (tid < TMR) bsh[tid] = batch[m0 + tid];
    #pragma unroll
    for (int s = 0; s < 4; s++) {
        int i = tid + s * 512;
        int x = i >> 10, k = (i >> 5) & 31, r = i & 31;
        Fk[i] = g_F[(m0 + r) * H_ + x * 32 + k] * 0.125f;
    }
    __syncthreads();

    const int bmin = bsh[0], bmax = bsh[TMR - 1];
    const int nb = bmax - bmin + 1;
    const bool uni = (nb == 1);
    const int total = nb * 4;

    // prologue: issue chunks 0..2
    issue_chunk(buf, g_BF + (bmin + 0) * (H_ * N_), 0, tid);
    issue_chunk(buf, g_BF + (bmin + 0) * (H_ * N_), 1, tid);
    issue_chunk(buf, g_BF + (bmin + 0) * (H_ * N_), 2, tid);

    const int half = w >> 3;            // 0:e (h 0..31), 1:g (h 32..63)
    const int rb   = (l >> 3) * 8;      // lane's 8 rows
    const int n0   = (w & 7) * 64 + (l & 7) * 8;   // lane's 8 n

    float2 acc[8][4];
    #pragma unroll
    for (int r = 0; r < 8; r++)
        #pragma unroll
        for (int p = 0; p < 4; p++) acc[r][p] = dup(0.f);

    // =================== pass 1: scores (register-resident) ================
    for (int step = 0; step < total; step++) {
        CP_WAIT2();
        __syncthreads();
        if (!uni && (step & 3) == 0) {
            int bc = bmin + (step >> 2);
            #pragma unroll
            for (int s = 0; s < 4; s++) {
                int i = tid + s * 512;
                FkM[i] = (bsh[i & 31] == bc) ? Fk[i] : 0.f;
            }
            __syncthreads();
        }
        if (step + 3 < total)
            issue_chunk(buf, g_BF + (bmin + ((step + 3) >> 2)) * (H_ * N_), step + 3, tid);
        else
            CP_COMMIT();   // keep group count uniform

        const float* fb = (uni ? Fk : FkM) + half * 1024 + rb;
        const float* tb = buf + (step & 3) * 8320 + half * 8 * 520 + n0;
        const int kb = (step & 3) * 8;
        #pragma unroll
        for (int kk = 0; kk < 8; kk++) {
            float4 bva = *(const float4*)(tb + kk * 520);
            float4 bvb = *(const float4*)(tb + kk * 520 + 4);
            float4 fa  = *(const float4*)(fb + (kb + kk) * 32);
            float4 fc  = *(const float4*)(fb + (kb + kk) * 32 + 4);
            float2 b0 = make_float2(bva.x, bva.y), b1 = make_float2(bva.z, bva.w);
            float2 b2 = make_float2(bvb.x, bvb.y), b3 = make_float2(bvb.z, bvb.w);
            const float fr[8] = {fa.x, fa.y, fa.z, fa.w, fc.x, fc.y, fc.z, fc.w};
            #pragma unroll
            for (int r = 0; r < 8; r++) {
                float2 fd = dup(fr[r]);
                fma2(acc[r][0], b0, fd);
                fma2(acc[r][1], b1, fd);
                fma2(acc[r][2], b2, fd);
                fma2(acc[r][3], b3, fd);
            }
        }
    }

    // =================== softmax (weights stay in registers) ===============
    float mrow[8];
    #pragma unroll
    for (int r = 0; r < 8; r++) {
        float m = fmaxf(fmaxf(fmaxf(acc[r][0].x, acc[r][0].y), fmaxf(acc[r][1].x, acc[r][1].y)),
                        fmaxf(fmaxf(acc[r][2].x, acc[r][2].y), fmaxf(acc[r][3].x, acc[r][3].y)));
        mrow[r] = m;
    }
    #pragma unroll
    for (int off = 4; off; off >>= 1)
        #pragma unroll
        for (int r = 0; r < 8; r++)
            mrow[r] = fmaxf(mrow[r], __shfl_xor_sync(0xffffffffu, mrow[r], off));
    if ((l & 7) == 0)
        #pragma unroll
        for (int r = 0; r < 8; r++)
            red[half * 256 + (w & 7) * 32 + rb + r] = mrow[r];
    __syncthreads();
    if (tid < 64) {
        int hh = tid >> 5, r = tid & 31;
        float m = -1e30f;
        #pragma unroll
        for (int ww = 0; ww < 8; ww++) m = fmaxf(m, red[hh * 256 + ww * 32 + r]);
        fin[tid] = m;
    }
    __syncthreads();

    float srow[8];
    #pragma unroll
    for (int r = 0; r < 8; r++) {
        float m = fin[half * 32 + rb + r];
        float s = 0.f;
        #pragma unroll
        for (int p = 0; p < 4; p++) {
            acc[r][p].x = __expf(acc[r][p].x - m);
            acc[r][p].y = __expf(acc[r][p].y - m);
            s += acc[r][p].x + acc[r][p].y;
        }
        srow[r] = s;
    }
    #pragma unroll
    for (int off = 4; off; off >>= 1)
        #pragma unroll
        for (int r = 0; r < 8; r++)
            srow[r] += __shfl_xor_sync(0xffffffffu, srow[r], off);
    if ((l & 7) == 0)
        #pragma unroll
        for (int r = 0; r < 8; r++)
            red[half * 256 + (w & 7) * 32 + rb + r] = srow[r];
    __syncthreads();
    if (tid < 64) {
        int hh = tid >> 5, r = tid & 31;
        float s = 0.f;
        #pragma unroll
        for (int ww = 0; ww < 8; ww++) s += red[hh * 256 + ww * 32 + r];
        rinv[tid] = 1.f / s;
    }

    // =================== pass 2: y[r][c] = bv_in[b] @ w[r] (6-dim trick) ===
    #pragma unroll
    for (int cg = 0; cg < 2; cg++) {
        float2 y3[8][3];
        #pragma unroll
        for (int r = 0; r < 8; r++)
            #pragma unroll
            for (int c = 0; c < 3; c++) y3[r][c] = dup(0.f);

        for (int bc = bmin; bc <= bmax; bc++) {
            __syncthreads();
            for (int i = tid; i < 1536; i += NTHR) {
                int c = i >> 9, n = i & 511;
                bvs[c * 520 + n] = bvin[bc * 6 * N_ + (cg * 3 + c) * N_ + n];
            }
            __syncthreads();

            bool msk[8];
            #pragma unroll
            for (int r = 0; r < 8; r++) msk[r] = uni || (bsh[rb + r] == bc);

            #pragma unroll
            for (int c = 0; c < 3; c++) {
                float4 va = *(const float4*)(bvs + c * 520 + n0);
                float4 vb = *(const float4*)(bvs + c * 520 + n0 + 4);
                float2 v0 = make_float2(va.x, va.y), v1 = make_float2(va.z, va.w);
                float2 v2 = make_float2(vb.x, vb.y), v3 = make_float2(vb.z, vb.w);
                #pragma unroll
                for (int r = 0; r < 8; r++) {
                    if (msk[r]) {
                        fma2(y3[r][c], acc[r][0], v0);
                        fma2(y3[r][c], acc[r][1], v1);
                        fma2(y3[r][c], acc[r][2], v2);
                        fma2(y3[r][c], acc[r][3], v3);
                    }
                }
            }
        }

        float yv[8][3];
        #pragma unroll
        for (int r = 0; r < 8; r++)
            #pragma unroll
            for (int c = 0; c < 3; c++) yv[r][c] = y3[r][c].x + y3[r][c].y;
        #pragma unroll
        for (int off = 4; off; off >>= 1)
            #pragma unroll
            for (int r = 0; r < 8; r++)
                #pragma unroll
                for (int c = 0; c < 3; c++)
                    yv[r][c] += __shfl_xor_sync(0xffffffffu, yv[r][c], off);
        if ((l & 7) == 0)
            #pragma unroll
            for (int r = 0; r < 8; r++)
                #pragma unroll
                for (int c = 0; c < 3; c++)
                    ypart[((half * 8 + (w & 7)) * 32 + rb + r) * 6 + cg * 3 + c] = yv[r][c];
        __syncthreads();
        if (tid < 192) {
            int hh = tid / 96, rem = tid % 96, rr = rem / 3, cc = rem % 3;
            float s = 0.f;
            #pragma unroll
            for (int ww = 0; ww < 8; ww++)
                s += ypart[((hh * 8 + ww) * 32 + rr) * 6 + cg * 3 + cc];
            yfin[(hh * 32 + rr) * 6 + cg * 3 + cc] = s * rinv[hh * 32 + rr];
        }
        __syncthreads();
    }

    // =================== cat[r][h] = Wbv @ y + bbv =========================
    {
        int r = tid >> 4, hq = (tid & 15) * 4;
        #pragma unroll
        for (int hh = 0; hh < 4; hh++) {
            int h = hq + hh;
            float se = 0.f, sg = 0.f;
            #pragma unroll
            for (int c = 0; c < 6; c++) {
                float wv = __ldg(Wbv + h * 6 + c);
                se += wv * yfin[r * 6 + c];
                sg += wv * yfin[(32 + r) * 6 + c];
            }
            float bb2 = __ldg(bbv + h);
            cat[r * 132 + h]      = se + bb2;
            cat[r * 132 + 64 + h] = sg + bb2;
        }
    }
    __syncthreads();

    // =================== pass 3: out = cat @ Wo.T + bo =====================
    for (int i = tid; i < 8192; i += NTHR) {
        int j = i >> 7, k = i & 127;
        WoT[k * 68 + j] = Wo[i];
    }
    __syncthreads();
    {
        const int j0 = (w & 1) * 32 + (l & 7) * 4;
        const int r  = (w >> 1) * 4 + (l >> 3);
        const float* cr = cat + r * 132;
        float2 olo = dup(0.f), ohi = dup(0.f);
        #pragma unroll 4
        for (int k4 = 0; k4 < 128; k4 += 4) {
            float4 c4 = *(const float4*)(cr + k4);
            const float cs[4] = {c4.x, c4.y, c4.z, c4.w};
            #pragma unroll
            for (int kk = 0; kk < 4; kk++) {
                float4 w4 = *(const float4*)(WoT + (k4 + kk) * 68 + j0);
                float2 cd = dup(cs[kk]);
                fma2(olo, make_float2(w4.x, w4.y), cd);
                fma2(ohi, make_float2(w4.z, w4.w), cd);
            }
        }
        float4 o = make_float4(olo.x + __ldg(bo + j0),     olo.y + __ldg(bo + j0 + 1),
                               ohi.x + __ldg(bo + j0 + 2), ohi.y + __ldg(bo + j0 + 3));
        *(float4*)(out + (m0 + r) * H_ + j0) = o;
    }
}

// ------------------------------ launch -------------------------------------
extern "C" void kernel_launch(void* const* d_in, const int* in_sizes, int n_in,
                              void* d_out, int out_size)
{
    const float* fin  = (const float*)d_in[0];
    const int*   batch= (const int*)  d_in[1];
    const float* bpre = (const float*)d_in[2];
    const float* bvin = (const float*)d_in[3];
    const float* Wf   = (const float*)d_in[4];
    const float* bf   = (const float*)d_in[5];
    const float* Wb   = (const float*)d_in[6];
    const float* bb   = (const float*)d_in[7];
    const float* Wbv  = (const float*)d_in[8];
    const float* bbv  = (const float*)d_in[9];
    const float* Wo   = (const float*)d_in[10];
    const float* bo   = (const float*)d_in[11];
    float* out = (float*)d_out;

    const int psm = 17408 * sizeof(float);    // 69.6 KB
    const int msm = 43032 * sizeof(float);    // 172.1 KB
    cudaFuncSetAttribute(prep_all_kernel, cudaFuncAttributeMaxDynamicSharedMemorySize, psm);
    cudaFuncSetAttribute(main_kernel, cudaFuncAttributeMaxDynamicSharedMemorySize, msm);

    prep_all_kernel<<<128, 256, psm>>>(fin, Wf, bf, bpre, Wb, bb);
    main_kernel<<<M_ / TMR, NTHR, msm>>>(batch, bvin, Wbv, bbv, Wo, bo, out);
}